// round 7
// baseline (speedup 1.0000x reference)
#include <cuda_runtime.h>
#include <cuda_bf16.h>
#include <cstdint>

#define NMAX 100000
#define EMAX 3200000

// Scratch (device globals: allocation is forbidden).
__device__ float g_deg[NMAX];
__device__ float g_dis[NMAX];
__device__ float g_xs[NMAX];            // dis * x (layer-1 scaled input)
__device__ int   g_cnt[NMAX];
__device__ int   g_rs[NMAX + 1];
__device__ int   g_cur[NMAX];
__device__ unsigned long long g_sstate[128];   // lookback scan state
__device__ uint2 g_edges[EMAX];         // packed {src, ea}
__device__ float g_bufA[NMAX * 64];
__device__ float g_bufB[NMAX * 64];
__device__ float g_t1[NMAX * 64];
__device__ float g_t1s[NMAX];           // dis * t1 (layer-1 chain)
__device__ float g_t2[NMAX * 64];
__device__ __nv_bfloat16 g_xb[NMAX * 32];   // bf16 shadow (dis-scaled)
__device__ __nv_bfloat16 g_tb[NMAX * 32];   // bf16 shadow of t1 (dis-scaled)

static inline int cdiv(long long a, int b) { return (int)((a + b - 1) / b); }

// ---------------------------------------------------------------------------
// fused zero of deg/cnt + scan state
// ---------------------------------------------------------------------------
__global__ void zero_build_k(float* deg, int* cnt, unsigned long long* sstate, int n) {
    int i = blockIdx.x * blockDim.x + threadIdx.x;
    if (i < n) { deg[i] = 0.f; cnt[i] = 0; }
    if (i < 128) sstate[i] = 0ULL;
}

// ---------------------------------------------------------------------------
// deg[src[e]] += ea[e];  cnt[dst[e]] += 1
// ---------------------------------------------------------------------------
__global__ void deg_hist_k(const int* __restrict__ src, const int* __restrict__ dst,
                           const float* __restrict__ ea,
                           float* __restrict__ deg, int* __restrict__ cnt, int E) {
    int e = blockIdx.x * blockDim.x + threadIdx.x;
    if (e >= E) return;
    atomicAdd(&deg[src[e]], ea[e]);
    atomicAdd(&cnt[dst[e]], 1);
}

// ---------------------------------------------------------------------------
// dis[i] = deg>0 ? rsqrt(deg) : 0 ; xs[i] = dis[i]*x[i]
// ---------------------------------------------------------------------------
__global__ void dis_k(const float* __restrict__ deg, const float* __restrict__ x,
                      float* __restrict__ dis, float* __restrict__ xs, int n) {
    int i = blockIdx.x * blockDim.x + threadIdx.x;
    if (i >= n) return;
    float d = deg[i];
    float r = d > 0.f ? rsqrtf(d) : 0.f;
    dis[i] = r;
    xs[i] = r * x[i];
}

// ---------------------------------------------------------------------------
// Single-pass decoupled-lookback exclusive scan of cnt -> rs, cur.
// 1024 elems/block; all blocks co-resident (98 blocks on 148 SMs).
// State word: bits[62:64)=status (0 none, 1 aggregate, 2 inclusive),
//             bits[0:32)=value.
// ---------------------------------------------------------------------------
#define SCAN_TPB 256
#define SCAN_ELEMS 1024

__global__ void scan_lookback_k(const int* __restrict__ cnt,
                                unsigned long long* __restrict__ sstate,
                                int* __restrict__ rs, int* __restrict__ cur, int n) {
    int b = blockIdx.x;
    int base = b * SCAN_ELEMS + threadIdx.x * 4;
    int c0 = 0, c1 = 0, c2 = 0, c3 = 0;
    if (base + 3 < n) {
        int4 v = *reinterpret_cast<const int4*>(cnt + base);
        c0 = v.x; c1 = v.y; c2 = v.z; c3 = v.w;
    } else {
        if (base + 0 < n) c0 = cnt[base + 0];
        if (base + 1 < n) c1 = cnt[base + 1];
        if (base + 2 < n) c2 = cnt[base + 2];
        if (base + 3 < n) c3 = cnt[base + 3];
    }
    int ts = c0 + c1 + c2 + c3;
    int lane = threadIdx.x & 31, wid = threadIdx.x >> 5;
    int inc = ts;
#pragma unroll
    for (int o = 1; o < 32; o <<= 1) {
        int v = __shfl_up_sync(0xffffffffu, inc, o);
        if (lane >= o) inc += v;
    }
    __shared__ int wsum[SCAN_TPB / 32];
    __shared__ int woff[SCAN_TPB / 32];
    __shared__ int s_base;
    __shared__ int s_total;
    if (lane == 31) wsum[wid] = inc;
    __syncthreads();
    if (threadIdx.x == 0) {
        int r = 0;
#pragma unroll
        for (int w = 0; w < SCAN_TPB / 32; w++) { woff[w] = r; r += wsum[w]; }
        s_total = r;
        // publish aggregate
        atomicExch(&sstate[b], (1ULL << 62) | (unsigned)r);
        // lookback
        int excl = 0;
        for (int p = b - 1; p >= 0; ) {
            unsigned long long s;
            do { s = atomicAdd(&sstate[p], 0ULL); } while ((s >> 62) == 0);
            excl += (int)(unsigned)s;
            if ((s >> 62) == 2ULL) break;
            p--;
        }
        // publish inclusive
        atomicExch(&sstate[b], (2ULL << 62) | (unsigned)(excl + r));
        s_base = excl;
    }
    __syncthreads();
    int r = s_base + (inc - ts) + woff[wid];
    if (base + 0 < n) { rs[base + 0] = r; cur[base + 0] = r; r += c0; }
    if (base + 1 < n) { rs[base + 1] = r; cur[base + 1] = r; r += c1; }
    if (base + 2 < n) { rs[base + 2] = r; cur[base + 2] = r; r += c2; }
    if (base + 3 < n) { rs[base + 3] = r; cur[base + 3] = r; r += c3; }
    if (b == gridDim.x - 1 && threadIdx.x == 0) rs[n] = s_base + s_total;
}

// ---------------------------------------------------------------------------
// scatter: records are just {src, ea} — no deg dependency.
// ---------------------------------------------------------------------------
__global__ void scatter_k(const int* __restrict__ src, const int* __restrict__ dst,
                          const float* __restrict__ ea,
                          int* __restrict__ cur, uint2* __restrict__ ed, int E) {
    int e = blockIdx.x * blockDim.x + threadIdx.x;
    if (e >= E) return;
    int d = dst[e];
    int slot = atomicAdd(&cur[d], 1);
    ed[slot] = make_uint2((unsigned)src[e], __float_as_uint(ea[e]));
}

// ---------------------------------------------------------------------------
// C == 1 props.
// ---------------------------------------------------------------------------
template <bool WRITE_S>
__global__ void prop_c1(const float* __restrict__ xs, const float* __restrict__ dis,
                        const uint2* __restrict__ ed, const int* __restrict__ rs,
                        float* __restrict__ out, float* __restrict__ outs, int N) {
    int warp = (blockIdx.x * blockDim.x + threadIdx.x) >> 5;
    int lane = threadIdx.x & 31;
    if (warp >= N) return;
    int beg = rs[warp], end = rs[warp + 1];
    float acc = 0.f;
    for (int j = beg + lane; j < end; j += 32) {
        uint2 e = ed[j];
        acc += __uint_as_float(e.y) * __ldg(xs + e.x);
    }
#pragma unroll
    for (int off = 16; off > 0; off >>= 1)
        acc += __shfl_down_sync(0xffffffffu, acc, off);
    if (lane == 0) {
        float di = dis[warp];
        float r = -di * acc;
        out[warp] = r;
        if (WRITE_S) outs[warp] = di * r;
    }
}

// ---------------------------------------------------------------------------
// bf16 CSR gather, C == 16: 4 lanes per edge (bf16x4 per lane), 8 edges/instr.
// grp = lane>>2 (8 edge slots), sub = lane&3 (4-channel quad).
// ---------------------------------------------------------------------------
template <bool WRITE_B>
__global__ void prop_c16_bf16(const __nv_bfloat16* __restrict__ xb,
                              const float* __restrict__ dis,
                              const uint2* __restrict__ ed, const int* __restrict__ rs,
                              float* __restrict__ out, __nv_bfloat16* __restrict__ outb,
                              int N) {
    int warp = (blockIdx.x * blockDim.x + threadIdx.x) >> 5;
    int lane = threadIdx.x & 31;
    if (warp >= N) return;
    int grp = lane >> 2;
    int sub = lane & 3;
    int beg = rs[warp], end = rs[warp + 1];
    float a0 = 0.f, a1 = 0.f, a2 = 0.f, a3 = 0.f;
    const char* xbp = reinterpret_cast<const char*>(xb);
    int j = beg;
    for (; j + 16 <= end; j += 16) {
        uint2 e0 = ed[j + grp];
        uint2 e1 = ed[j + 8 + grp];
        uint2 v0 = *reinterpret_cast<const uint2*>(xbp + (size_t)e0.x * 32 + sub * 8);
        uint2 v1 = *reinterpret_cast<const uint2*>(xbp + (size_t)e1.x * 32 + sub * 8);
        float w0 = __uint_as_float(e0.y);
        float w1 = __uint_as_float(e1.y);
        float2 f0a = __bfloat1622float2(*reinterpret_cast<__nv_bfloat162*>(&v0.x));
        float2 f0b = __bfloat1622float2(*reinterpret_cast<__nv_bfloat162*>(&v0.y));
        float2 f1a = __bfloat1622float2(*reinterpret_cast<__nv_bfloat162*>(&v1.x));
        float2 f1b = __bfloat1622float2(*reinterpret_cast<__nv_bfloat162*>(&v1.y));
        a0 = fmaf(w0, f0a.x, a0); a1 = fmaf(w0, f0a.y, a1);
        a2 = fmaf(w0, f0b.x, a2); a3 = fmaf(w0, f0b.y, a3);
        a0 = fmaf(w1, f1a.x, a0); a1 = fmaf(w1, f1a.y, a1);
        a2 = fmaf(w1, f1b.x, a2); a3 = fmaf(w1, f1b.y, a3);
    }
    for (; j < end; j += 8) {
        int idx = j + grp;
        if (idx < end) {
            uint2 e = ed[idx];
            uint2 v = *reinterpret_cast<const uint2*>(xbp + (size_t)e.x * 32 + sub * 8);
            float w = __uint_as_float(e.y);
            float2 fa = __bfloat1622float2(*reinterpret_cast<__nv_bfloat162*>(&v.x));
            float2 fb = __bfloat1622float2(*reinterpret_cast<__nv_bfloat162*>(&v.y));
            a0 = fmaf(w, fa.x, a0); a1 = fmaf(w, fa.y, a1);
            a2 = fmaf(w, fb.x, a2); a3 = fmaf(w, fb.y, a3);
        }
    }
#pragma unroll
    for (int off = 4; off <= 16; off <<= 1) {
        a0 += __shfl_xor_sync(0xffffffffu, a0, off);
        a1 += __shfl_xor_sync(0xffffffffu, a1, off);
        a2 += __shfl_xor_sync(0xffffffffu, a2, off);
        a3 += __shfl_xor_sync(0xffffffffu, a3, off);
    }
    if (lane < 4) {
        float di = dis[warp];
        float4 r; r.x = -di * a0; r.y = -di * a1; r.z = -di * a2; r.w = -di * a3;
        *reinterpret_cast<float4*>(out + (size_t)warp * 16 + sub * 4) = r;
        if (WRITE_B) {
            __nv_bfloat162 p0 = __floats2bfloat162_rn(di * r.x, di * r.y);
            __nv_bfloat162 p1 = __floats2bfloat162_rn(di * r.z, di * r.w);
            uint2 pk;
            pk.x = *reinterpret_cast<unsigned*>(&p0);
            pk.y = *reinterpret_cast<unsigned*>(&p1);
            *reinterpret_cast<uint2*>(
                reinterpret_cast<char*>(outb) + (size_t)warp * 32 + sub * 8) = pk;
        }
    }
}

// ---------------------------------------------------------------------------
// bf16 CSR gather, C == 32: 8 lanes per edge (bf16x4 per lane), 4 edges/instr.
// grp = lane>>3 (4 edge slots), sub = lane&7 (4-channel quad).
// ---------------------------------------------------------------------------
template <bool WRITE_B>
__global__ void prop_c32_bf16(const __nv_bfloat16* __restrict__ xb,
                              const float* __restrict__ dis,
                              const uint2* __restrict__ ed, const int* __restrict__ rs,
                              float* __restrict__ out, __nv_bfloat16* __restrict__ outb,
                              int N) {
    int warp = (blockIdx.x * blockDim.x + threadIdx.x) >> 5;
    int lane = threadIdx.x & 31;
    if (warp >= N) return;
    int grp = lane >> 3;
    int sub = lane & 7;
    int beg = rs[warp], end = rs[warp + 1];
    float a0 = 0.f, a1 = 0.f, a2 = 0.f, a3 = 0.f;
    const char* xbp = reinterpret_cast<const char*>(xb);
    int j = beg;
    for (; j + 16 <= end; j += 16) {
        uint2 e[4];
#pragma unroll
        for (int k = 0; k < 4; k++) e[k] = ed[j + k * 4 + grp];
        uint2 v[4];
#pragma unroll
        for (int k = 0; k < 4; k++)
            v[k] = *reinterpret_cast<const uint2*>(xbp + (size_t)e[k].x * 64 + sub * 8);
#pragma unroll
        for (int k = 0; k < 4; k++) {
            float w = __uint_as_float(e[k].y);
            float2 fa = __bfloat1622float2(*reinterpret_cast<__nv_bfloat162*>(&v[k].x));
            float2 fb = __bfloat1622float2(*reinterpret_cast<__nv_bfloat162*>(&v[k].y));
            a0 = fmaf(w, fa.x, a0); a1 = fmaf(w, fa.y, a1);
            a2 = fmaf(w, fb.x, a2); a3 = fmaf(w, fb.y, a3);
        }
    }
    for (; j < end; j += 4) {
        int idx = j + grp;
        if (idx < end) {
            uint2 e = ed[idx];
            uint2 v = *reinterpret_cast<const uint2*>(xbp + (size_t)e.x * 64 + sub * 8);
            float w = __uint_as_float(e.y);
            float2 fa = __bfloat1622float2(*reinterpret_cast<__nv_bfloat162*>(&v.x));
            float2 fb = __bfloat1622float2(*reinterpret_cast<__nv_bfloat162*>(&v.y));
            a0 = fmaf(w, fa.x, a0); a1 = fmaf(w, fa.y, a1);
            a2 = fmaf(w, fb.x, a2); a3 = fmaf(w, fb.y, a3);
        }
    }
#pragma unroll
    for (int off = 8; off <= 16; off <<= 1) {
        a0 += __shfl_xor_sync(0xffffffffu, a0, off);
        a1 += __shfl_xor_sync(0xffffffffu, a1, off);
        a2 += __shfl_xor_sync(0xffffffffu, a2, off);
        a3 += __shfl_xor_sync(0xffffffffu, a3, off);
    }
    if (lane < 8) {
        float di = dis[warp];
        float4 r; r.x = -di * a0; r.y = -di * a1; r.z = -di * a2; r.w = -di * a3;
        *reinterpret_cast<float4*>(out + (size_t)warp * 32 + sub * 4) = r;
        if (WRITE_B) {
            __nv_bfloat162 p0 = __floats2bfloat162_rn(di * r.x, di * r.y);
            __nv_bfloat162 p1 = __floats2bfloat162_rn(di * r.z, di * r.w);
            uint2 pk;
            pk.x = *reinterpret_cast<unsigned*>(&p0);
            pk.y = *reinterpret_cast<unsigned*>(&p1);
            *reinterpret_cast<uint2*>(
                reinterpret_cast<char*>(outb) + (size_t)warp * 64 + sub * 8) = pk;
        }
    }
}

// ---------------------------------------------------------------------------
// C == 4 prop of zpack (dis-scaled [z1|z2]).
// ---------------------------------------------------------------------------
__global__ void prop_csr_c4(const float* __restrict__ zs, const float* __restrict__ dis,
                            const uint2* __restrict__ ed, const int* __restrict__ rs,
                            float* __restrict__ out, int N) {
    int warp = (blockIdx.x * blockDim.x + threadIdx.x) >> 5;
    int lane = threadIdx.x & 31;
    if (warp >= N) return;
    int k = lane >> 2;
    int c = lane & 3;
    int beg = rs[warp], end = rs[warp + 1];
    float acc = 0.f;
    for (int j = beg + k; j < end; j += 8) {
        uint2 e = ed[j];
        acc = fmaf(__uint_as_float(e.y), __ldg(zs + (size_t)e.x * 4 + c), acc);
    }
#pragma unroll
    for (int off = 16; off >= 4; off >>= 1)
        acc += __shfl_down_sync(0xffffffffu, acc, off);
    if (lane < 4) {
        float di = dis[warp];
        float r = -di * acc;
        out[(size_t)warp * 4 + c] = (c < 2) ? r : di * r;
    }
}

// ---------------------------------------------------------------------------
// Final tail: y = part + t4[:,0:2] + 2 * (-dis[d] * sum ea * t4[s, 2+c])
// ---------------------------------------------------------------------------
__global__ void prop2_final_k(const float* __restrict__ t4, const float* __restrict__ part,
                              const float* __restrict__ dis,
                              const uint2* __restrict__ ed, const int* __restrict__ rs,
                              float* __restrict__ y, int N) {
    int warp = (blockIdx.x * blockDim.x + threadIdx.x) >> 5;
    int lane = threadIdx.x & 31;
    if (warp >= N) return;
    int k = lane >> 1;
    int c = lane & 1;
    int beg = rs[warp], end = rs[warp + 1];
    float acc = 0.f;
    for (int j = beg + k; j < end; j += 16) {
        uint2 e = ed[j];
        acc = fmaf(__uint_as_float(e.y), __ldg(t4 + (size_t)e.x * 4 + 2 + c), acc);
    }
#pragma unroll
    for (int off = 16; off >= 2; off >>= 1)
        acc += __shfl_down_sync(0xffffffffu, acc, off);
    if (lane < 2) {
        float w = -dis[warp] * acc;
        y[(size_t)warp * 2 + c] = part[(size_t)warp * 2 + c]
                                + t4[(size_t)warp * 4 + c] + 2.f * w;
    }
}

// ---------------------------------------------------------------------------
// Layer-4 head GEMM: part = h@W0 - h@W2 ; zpack = dis[n]*[h@W1 | h@W2]
// ---------------------------------------------------------------------------
__global__ void gemm_head_64_2(const float* __restrict__ h, const float* __restrict__ dis,
                               const float* __restrict__ W,
                               float* __restrict__ part, float* __restrict__ zpack, int n) {
    __shared__ float sW[6 * 64];
    for (int i = threadIdx.x; i < 384; i += blockDim.x) {
        int k = i / 128, rem = i % 128, ci = rem / 2, co = rem % 2;
        sW[(k * 2 + co) * 64 + ci] = W[i];
    }
    __syncthreads();
    int warp = (blockIdx.x * blockDim.x + threadIdx.x) >> 5;
    int lane = threadIdx.x & 31;
    if (warp >= n) return;
    size_t base = (size_t)warp * 64;
    float a0 = h[base + lane];
    float a1 = h[base + lane + 32];
    float r[6];
#pragma unroll
    for (int m = 0; m < 6; m++) {
        const float* w = sW + m * 64;
        float acc = fmaf(a1, w[lane + 32], a0 * w[lane]);
#pragma unroll
        for (int off = 16; off > 0; off >>= 1)
            acc += __shfl_down_sync(0xffffffffu, acc, off);
        r[m] = acc;
    }
    if (lane == 0) {
        float di = dis[warp];
        part[(size_t)warp * 2 + 0] = r[0] - r[4];
        part[(size_t)warp * 2 + 1] = r[1] - r[5];
        float4 z; z.x = di * r[2]; z.y = di * r[3]; z.z = di * r[4]; z.w = di * r[5];
        *reinterpret_cast<float4*>(zpack + (size_t)warp * 4) = z;
    }
}

// ---------------------------------------------------------------------------
// Combine 1->16: emits fp32 out and dis-scaled bf16 shadow
// ---------------------------------------------------------------------------
__global__ void combine_1_16(const float* __restrict__ f0, const float* __restrict__ t1,
                             const float* __restrict__ t2, const float* __restrict__ dis,
                             const float* __restrict__ W,
                             float* __restrict__ out, __nv_bfloat16* __restrict__ outb,
                             int n) {
    __shared__ float sW[48];
    if (threadIdx.x < 48) sW[threadIdx.x] = W[threadIdx.x];
    __syncthreads();
    int tid = blockIdx.x * blockDim.x + threadIdx.x;
    int node = tid >> 4;
    int co = tid & 15;
    if (node >= n) return;
    float a = f0[node];
    float b = t1[node];
    float d = 2.f * t2[node] - a;
    float acc = a * sW[co] + b * sW[16 + co] + d * sW[32 + co];
    float r = fmaxf(acc, 0.f);
    out[(size_t)node * 16 + co] = r;
    outb[(size_t)node * 16 + co] = __float2bfloat16_rn(dis[node] * r);
}

// ---------------------------------------------------------------------------
// Combine 16->32: warp per node; emits dis-scaled bf16 shadow
// ---------------------------------------------------------------------------
__global__ void combine_16_32(const float* __restrict__ f0, const float* __restrict__ t1,
                              const float* __restrict__ t2, const float* __restrict__ dis,
                              const float* __restrict__ W,
                              float* __restrict__ out, __nv_bfloat16* __restrict__ outb,
                              int n) {
    __shared__ float sW[3 * 16 * 32];
    for (int i = threadIdx.x; i < 3 * 16 * 32; i += blockDim.x) sW[i] = W[i];
    __syncthreads();
    int warp = (blockIdx.x * blockDim.x + threadIdx.x) >> 5;
    int lane = threadIdx.x & 31;
    if (warp >= n) return;
    int c = lane & 15;
    float a = f0[(size_t)warp * 16 + c];
    float b = t1[(size_t)warp * 16 + c];
    float d = 2.f * t2[(size_t)warp * 16 + c] - a;
    float acc = 0.f;
#pragma unroll
    for (int cc = 0; cc < 16; cc++) {
        float av = __shfl_sync(0xffffffffu, a, cc);
        float bv = __shfl_sync(0xffffffffu, b, cc);
        float dv = __shfl_sync(0xffffffffu, d, cc);
        acc = fmaf(av, sW[cc * 32 + lane], acc);
        acc = fmaf(bv, sW[512 + cc * 32 + lane], acc);
        acc = fmaf(dv, sW[1024 + cc * 32 + lane], acc);
    }
    float r = fmaxf(acc, 0.f);
    out[(size_t)warp * 32 + lane] = r;
    outb[(size_t)warp * 32 + lane] = __float2bfloat16_rn(dis[warp] * r);
}

// ---------------------------------------------------------------------------
// Combine 32->64: warp per node (fp32 only)
// ---------------------------------------------------------------------------
__global__ void combine_32_64(const float* __restrict__ f0, const float* __restrict__ t1,
                              const float* __restrict__ t2, const float* __restrict__ W,
                              float* __restrict__ out, int n) {
    __shared__ float sW[3 * 32 * 64];
    for (int i = threadIdx.x; i < 3 * 32 * 64; i += blockDim.x) sW[i] = W[i];
    __syncthreads();
    int warp = (blockIdx.x * blockDim.x + threadIdx.x) >> 5;
    int lane = threadIdx.x & 31;
    if (warp >= n) return;
    float a = f0[(size_t)warp * 32 + lane];
    float b = t1[(size_t)warp * 32 + lane];
    float d = 2.f * t2[(size_t)warp * 32 + lane] - a;
    float acc0 = 0.f, acc1 = 0.f;
#pragma unroll
    for (int cc = 0; cc < 32; cc++) {
        float av = __shfl_sync(0xffffffffu, a, cc);
        float bv = __shfl_sync(0xffffffffu, b, cc);
        float dv = __shfl_sync(0xffffffffu, d, cc);
        const float* w0 = sW + cc * 64;
        const float* w1 = sW + 2048 + cc * 64;
        const float* w2 = sW + 4096 + cc * 64;
        acc0 = fmaf(av, w0[lane], acc0);
        acc0 = fmaf(bv, w1[lane], acc0);
        acc0 = fmaf(dv, w2[lane], acc0);
        acc1 = fmaf(av, w0[lane + 32], acc1);
        acc1 = fmaf(bv, w1[lane + 32], acc1);
        acc1 = fmaf(dv, w2[lane + 32], acc1);
    }
    out[(size_t)warp * 64 + lane] = fmaxf(acc0, 0.f);
    out[(size_t)warp * 64 + lane + 32] = fmaxf(acc1, 0.f);
}

extern "C" void kernel_launch(void* const* d_in, const int* in_sizes, int n_in,
                              void* d_out, int out_size) {
    const float* x = (const float*)d_in[0];
    const int* edge_index = (const int*)d_in[1];
    const float* ea = (const float*)d_in[2];
    const float* W1 = (const float*)d_in[3];
    const float* W2 = (const float*)d_in[4];
    const float* W3 = (const float*)d_in[5];
    const float* W4 = (const float*)d_in[6];

    const int N = in_sizes[0];
    const int E = in_sizes[2];
    const int* src = edge_index;
    const int* dst = edge_index + E;

    float *deg, *dis, *xs, *bufA, *bufB, *t1, *t1s, *t2;
    int *cnt, *rs, *cur;
    unsigned long long* sstate;
    uint2* edges;
    __nv_bfloat16 *xb, *tb;
    cudaGetSymbolAddress((void**)&deg, g_deg);
    cudaGetSymbolAddress((void**)&dis, g_dis);
    cudaGetSymbolAddress((void**)&xs, g_xs);
    cudaGetSymbolAddress((void**)&cnt, g_cnt);
    cudaGetSymbolAddress((void**)&rs, g_rs);
    cudaGetSymbolAddress((void**)&cur, g_cur);
    cudaGetSymbolAddress((void**)&sstate, g_sstate);
    cudaGetSymbolAddress((void**)&edges, g_edges);
    cudaGetSymbolAddress((void**)&bufA, g_bufA);
    cudaGetSymbolAddress((void**)&bufB, g_bufB);
    cudaGetSymbolAddress((void**)&t1, g_t1);
    cudaGetSymbolAddress((void**)&t1s, g_t1s);
    cudaGetSymbolAddress((void**)&t2, g_t2);
    cudaGetSymbolAddress((void**)&xb, g_xb);
    cudaGetSymbolAddress((void**)&tb, g_tb);

    // ---- build CSR + dis ----
    zero_build_k<<<cdiv(N, 256), 256>>>(deg, cnt, sstate, N);
    deg_hist_k<<<cdiv(E, 256), 256>>>(src, dst, ea, deg, cnt, E);
    int nb = cdiv(N, SCAN_ELEMS);
    scan_lookback_k<<<nb, SCAN_TPB>>>(cnt, sstate, rs, cur, N);
    scatter_k<<<cdiv(E, 256), 256>>>(src, dst, ea, cur, edges, E);   // ncu-captured
    dis_k<<<cdiv(N, 256), 256>>>(deg, x, dis, xs, N);

    const int WPB = 256;
    int grid_n = cdiv((long long)N * 32, WPB);

    // ---- layer 1: 1 -> 16, relu ----
    prop_c1<true><<<grid_n, WPB>>>(xs, dis, edges, rs, t1, t1s, N);
    prop_c1<false><<<grid_n, WPB>>>(t1s, dis, edges, rs, t2, nullptr, N);
    combine_1_16<<<cdiv((long long)N * 16, 256), 256>>>(x, t1, t2, dis, W1, bufA, xb, N);

    // ---- layer 2: 16 -> 32, relu (bf16 gathers) ----
    prop_c16_bf16<true><<<grid_n, WPB>>>(xb, dis, edges, rs, t1, tb, N);
    prop_c16_bf16<false><<<grid_n, WPB>>>(tb, dis, edges, rs, t2, nullptr, N);
    combine_16_32<<<grid_n, WPB>>>(bufA, t1, t2, dis, W2, bufB, xb, N);

    // ---- layer 3: 32 -> 64, relu (bf16 gathers) ----
    prop_c32_bf16<true><<<grid_n, WPB>>>(xb, dis, edges, rs, t1, tb, N);
    prop_c32_bf16<false><<<grid_n, WPB>>>(tb, dis, edges, rs, t2, nullptr, N);
    combine_32_64<<<grid_n, WPB>>>(bufB, t1, t2, W3, bufA, N);

    // ---- layer 4: 64 -> 2 via project-then-propagate ----
    gemm_head_64_2<<<grid_n, WPB>>>(bufA, dis, W4, bufB, t1, N);
    prop_csr_c4<<<grid_n, WPB>>>(t1, dis, edges, rs, t2, N);
    prop2_final_k<<<grid_n, WPB>>>(t2, bufB, dis, edges, rs, (float*)d_out, N);
}

// round 8
// speedup vs baseline: 1.0297x; 1.0297x over previous
#include <cuda_runtime.h>
#include <cuda_bf16.h>
#include <cstdint>

#define NMAX 100000
#define EMAX 3200000

// Scratch (device globals: allocation is forbidden).
__device__ float g_deg[NMAX];
__device__ float g_dis[NMAX];
__device__ float g_xs[NMAX];            // dis * x (layer-1 scaled input)
__device__ int   g_cnt[NMAX];
__device__ int   g_rs[NMAX + 1];
__device__ int   g_cur[NMAX];
__device__ unsigned long long g_sstate[128];   // lookback scan state
__device__ uint2 g_edges[EMAX];         // packed {src, ea}
__device__ float g_bufA[NMAX * 64];
__device__ float g_bufB[NMAX * 64];
__device__ float g_t1[NMAX * 64];
__device__ float g_t1s[NMAX];           // dis * t1 (layer-1 chain)
__device__ float g_t2[NMAX * 64];
__device__ __nv_bfloat16 g_xb[NMAX * 32];   // bf16 shadow (dis-scaled)
__device__ __nv_bfloat16 g_tb[NMAX * 32];   // bf16 shadow of t1 (dis-scaled)

static inline int cdiv(long long a, int b) { return (int)((a + b - 1) / b); }

// ---------------------------------------------------------------------------
// fused zero of deg/cnt + scan state
// ---------------------------------------------------------------------------
__global__ void zero_build_k(float* deg, int* cnt, unsigned long long* sstate, int n) {
    int i = blockIdx.x * blockDim.x + threadIdx.x;
    if (i < n) { deg[i] = 0.f; cnt[i] = 0; }
    if (i < 128) sstate[i] = 0ULL;
}

// ---------------------------------------------------------------------------
// deg[src[e]] += ea[e];  cnt[dst[e]] += 1   — 4 edges per thread (MLP=4+)
// ---------------------------------------------------------------------------
__global__ void deg_hist_k(const int* __restrict__ src, const int* __restrict__ dst,
                           const float* __restrict__ ea,
                           float* __restrict__ deg, int* __restrict__ cnt, int E) {
    int base = (blockIdx.x * blockDim.x + threadIdx.x) * 4;
    if (base + 3 < E) {
        int4 s = *reinterpret_cast<const int4*>(src + base);
        int4 d = *reinterpret_cast<const int4*>(dst + base);
        float4 w = *reinterpret_cast<const float4*>(ea + base);
        atomicAdd(&deg[s.x], w.x);
        atomicAdd(&deg[s.y], w.y);
        atomicAdd(&deg[s.z], w.z);
        atomicAdd(&deg[s.w], w.w);
        atomicAdd(&cnt[d.x], 1);
        atomicAdd(&cnt[d.y], 1);
        atomicAdd(&cnt[d.z], 1);
        atomicAdd(&cnt[d.w], 1);
    } else {
        for (int e = base; e < E; e++) {
            atomicAdd(&deg[src[e]], ea[e]);
            atomicAdd(&cnt[dst[e]], 1);
        }
    }
}

// ---------------------------------------------------------------------------
// dis[i] = deg>0 ? rsqrt(deg) : 0 ; xs[i] = dis[i]*x[i]
// ---------------------------------------------------------------------------
__global__ void dis_k(const float* __restrict__ deg, const float* __restrict__ x,
                      float* __restrict__ dis, float* __restrict__ xs, int n) {
    int i = blockIdx.x * blockDim.x + threadIdx.x;
    if (i >= n) return;
    float d = deg[i];
    float r = d > 0.f ? rsqrtf(d) : 0.f;
    dis[i] = r;
    xs[i] = r * x[i];
}

// ---------------------------------------------------------------------------
// Single-pass decoupled-lookback exclusive scan of cnt -> rs, cur.
// ---------------------------------------------------------------------------
#define SCAN_TPB 256
#define SCAN_ELEMS 1024

__global__ void scan_lookback_k(const int* __restrict__ cnt,
                                unsigned long long* __restrict__ sstate,
                                int* __restrict__ rs, int* __restrict__ cur, int n) {
    int b = blockIdx.x;
    int base = b * SCAN_ELEMS + threadIdx.x * 4;
    int c0 = 0, c1 = 0, c2 = 0, c3 = 0;
    if (base + 3 < n) {
        int4 v = *reinterpret_cast<const int4*>(cnt + base);
        c0 = v.x; c1 = v.y; c2 = v.z; c3 = v.w;
    } else {
        if (base + 0 < n) c0 = cnt[base + 0];
        if (base + 1 < n) c1 = cnt[base + 1];
        if (base + 2 < n) c2 = cnt[base + 2];
        if (base + 3 < n) c3 = cnt[base + 3];
    }
    int ts = c0 + c1 + c2 + c3;
    int lane = threadIdx.x & 31, wid = threadIdx.x >> 5;
    int inc = ts;
#pragma unroll
    for (int o = 1; o < 32; o <<= 1) {
        int v = __shfl_up_sync(0xffffffffu, inc, o);
        if (lane >= o) inc += v;
    }
    __shared__ int wsum[SCAN_TPB / 32];
    __shared__ int woff[SCAN_TPB / 32];
    __shared__ int s_base;
    __shared__ int s_total;
    if (lane == 31) wsum[wid] = inc;
    __syncthreads();
    if (threadIdx.x == 0) {
        int r = 0;
#pragma unroll
        for (int w = 0; w < SCAN_TPB / 32; w++) { woff[w] = r; r += wsum[w]; }
        s_total = r;
        atomicExch(&sstate[b], (1ULL << 62) | (unsigned)r);
        int excl = 0;
        for (int p = b - 1; p >= 0; ) {
            unsigned long long s;
            do { s = atomicAdd(&sstate[p], 0ULL); } while ((s >> 62) == 0);
            excl += (int)(unsigned)s;
            if ((s >> 62) == 2ULL) break;
            p--;
        }
        atomicExch(&sstate[b], (2ULL << 62) | (unsigned)(excl + r));
        s_base = excl;
    }
    __syncthreads();
    int r = s_base + (inc - ts) + woff[wid];
    if (base + 0 < n) { rs[base + 0] = r; cur[base + 0] = r; r += c0; }
    if (base + 1 < n) { rs[base + 1] = r; cur[base + 1] = r; r += c1; }
    if (base + 2 < n) { rs[base + 2] = r; cur[base + 2] = r; r += c2; }
    if (base + 3 < n) { rs[base + 3] = r; cur[base + 3] = r; r += c3; }
    if (b == gridDim.x - 1 && threadIdx.x == 0) rs[n] = s_base + s_total;
}

// ---------------------------------------------------------------------------
// scatter: 4 edges per thread, records {src, ea}
// ---------------------------------------------------------------------------
__global__ void scatter_k(const int* __restrict__ src, const int* __restrict__ dst,
                          const float* __restrict__ ea,
                          int* __restrict__ cur, uint2* __restrict__ ed, int E) {
    int base = (blockIdx.x * blockDim.x + threadIdx.x) * 4;
    if (base + 3 < E) {
        int4 s = *reinterpret_cast<const int4*>(src + base);
        int4 d = *reinterpret_cast<const int4*>(dst + base);
        float4 w = *reinterpret_cast<const float4*>(ea + base);
        int p0 = atomicAdd(&cur[d.x], 1);
        int p1 = atomicAdd(&cur[d.y], 1);
        int p2 = atomicAdd(&cur[d.z], 1);
        int p3 = atomicAdd(&cur[d.w], 1);
        ed[p0] = make_uint2((unsigned)s.x, __float_as_uint(w.x));
        ed[p1] = make_uint2((unsigned)s.y, __float_as_uint(w.y));
        ed[p2] = make_uint2((unsigned)s.z, __float_as_uint(w.z));
        ed[p3] = make_uint2((unsigned)s.w, __float_as_uint(w.w));
    } else {
        for (int e = base; e < E; e++) {
            int slot = atomicAdd(&cur[dst[e]], 1);
            ed[slot] = make_uint2((unsigned)src[e], __float_as_uint(ea[e]));
        }
    }
}

// ---------------------------------------------------------------------------
// C == 1 props.
// ---------------------------------------------------------------------------
template <bool WRITE_S>
__global__ void prop_c1(const float* __restrict__ xs, const float* __restrict__ dis,
                        const uint2* __restrict__ ed, const int* __restrict__ rs,
                        float* __restrict__ out, float* __restrict__ outs, int N) {
    int warp = (blockIdx.x * blockDim.x + threadIdx.x) >> 5;
    int lane = threadIdx.x & 31;
    if (warp >= N) return;
    int beg = rs[warp], end = rs[warp + 1];
    float acc = 0.f;
    for (int j = beg + lane; j < end; j += 32) {
        uint2 e = ed[j];
        acc += __uint_as_float(e.y) * __ldg(xs + e.x);
    }
#pragma unroll
    for (int off = 16; off > 0; off >>= 1)
        acc += __shfl_down_sync(0xffffffffu, acc, off);
    if (lane == 0) {
        float di = dis[warp];
        float r = -di * acc;
        out[warp] = r;
        if (WRITE_S) outs[warp] = di * r;
    }
}

// ---------------------------------------------------------------------------
// bf16 CSR gather, C == 16 (round-6 form): half lanes on channels, 16-edge batch
// grp = lane>>3 (4 edge slots), sub = lane&7 (bf162 channel pair).
// ---------------------------------------------------------------------------
template <bool WRITE_B>
__global__ void prop_c16_bf16(const __nv_bfloat16* __restrict__ xb,
                              const float* __restrict__ dis,
                              const uint2* __restrict__ ed, const int* __restrict__ rs,
                              float* __restrict__ out, __nv_bfloat16* __restrict__ outb,
                              int N) {
    int warp = (blockIdx.x * blockDim.x + threadIdx.x) >> 5;
    int lane = threadIdx.x & 31;
    if (warp >= N) return;
    int grp = lane >> 3;
    int sub = lane & 7;
    int beg = rs[warp], end = rs[warp + 1];
    float ax = 0.f, ay = 0.f;
    int j = beg;
    for (; j + 16 <= end; j += 16) {
        uint2 e[4];
#pragma unroll
        for (int k = 0; k < 4; k++) e[k] = ed[j + k * 4 + grp];
        float2 f[4];
#pragma unroll
        for (int k = 0; k < 4; k++) {
            __nv_bfloat162 v = *reinterpret_cast<const __nv_bfloat162*>(
                xb + (size_t)e[k].x * 16 + sub * 2);
            f[k] = __bfloat1622float2(v);
        }
#pragma unroll
        for (int k = 0; k < 4; k++) {
            float w = __uint_as_float(e[k].y);
            ax = fmaf(w, f[k].x, ax);
            ay = fmaf(w, f[k].y, ay);
        }
    }
    for (; j < end; j += 4) {
        int idx = j + grp;
        if (idx < end) {
            uint2 e = ed[idx];
            __nv_bfloat162 v = *reinterpret_cast<const __nv_bfloat162*>(
                xb + (size_t)e.x * 16 + sub * 2);
            float2 f = __bfloat1622float2(v);
            float w = __uint_as_float(e.y);
            ax = fmaf(w, f.x, ax); ay = fmaf(w, f.y, ay);
        }
    }
    ax += __shfl_xor_sync(0xffffffffu, ax, 8);
    ay += __shfl_xor_sync(0xffffffffu, ay, 8);
    ax += __shfl_xor_sync(0xffffffffu, ax, 16);
    ay += __shfl_xor_sync(0xffffffffu, ay, 16);
    if (lane < 8) {
        float di = dis[warp];
        float2 r; r.x = -di * ax; r.y = -di * ay;
        *reinterpret_cast<float2*>(out + (size_t)warp * 16 + sub * 2) = r;
        if (WRITE_B) {
            float2 s; s.x = di * r.x; s.y = di * r.y;
            __nv_bfloat162 b = __float22bfloat162_rn(s);
            *reinterpret_cast<__nv_bfloat162*>(outb + (size_t)warp * 16 + sub * 2) = b;
        }
    }
}

// ---------------------------------------------------------------------------
// bf16 CSR gather, C == 32 (round-6 form): 16 lanes/edge, 16-edge batch
// grp = lane>>4 (2 edge slots), sub = lane&15 (bf162 channel pair).
// ---------------------------------------------------------------------------
template <bool WRITE_B>
__global__ void prop_c32_bf16(const __nv_bfloat16* __restrict__ xb,
                              const float* __restrict__ dis,
                              const uint2* __restrict__ ed, const int* __restrict__ rs,
                              float* __restrict__ out, __nv_bfloat16* __restrict__ outb,
                              int N) {
    int warp = (blockIdx.x * blockDim.x + threadIdx.x) >> 5;
    int lane = threadIdx.x & 31;
    if (warp >= N) return;
    int grp = lane >> 4;
    int sub = lane & 15;
    int beg = rs[warp], end = rs[warp + 1];
    float ax = 0.f, ay = 0.f;
    int j = beg;
    for (; j + 16 <= end; j += 16) {
        uint2 e[8];
#pragma unroll
        for (int k = 0; k < 8; k++) e[k] = ed[j + k * 2 + grp];
        float2 f[8];
#pragma unroll
        for (int k = 0; k < 8; k++) {
            __nv_bfloat162 v = *reinterpret_cast<const __nv_bfloat162*>(
                xb + (size_t)e[k].x * 32 + sub * 2);
            f[k] = __bfloat1622float2(v);
        }
#pragma unroll
        for (int k = 0; k < 8; k++) {
            float w = __uint_as_float(e[k].y);
            ax = fmaf(w, f[k].x, ax);
            ay = fmaf(w, f[k].y, ay);
        }
    }
    for (; j < end; j += 2) {
        int idx = j + grp;
        if (idx < end) {
            uint2 e = ed[idx];
            __nv_bfloat162 v = *reinterpret_cast<const __nv_bfloat162*>(
                xb + (size_t)e.x * 32 + sub * 2);
            float2 f = __bfloat1622float2(v);
            float w = __uint_as_float(e.y);
            ax = fmaf(w, f.x, ax); ay = fmaf(w, f.y, ay);
        }
    }
    ax += __shfl_xor_sync(0xffffffffu, ax, 16);
    ay += __shfl_xor_sync(0xffffffffu, ay, 16);
    if (lane < 16) {
        float di = dis[warp];
        float2 r; r.x = -di * ax; r.y = -di * ay;
        *reinterpret_cast<float2*>(out + (size_t)warp * 32 + sub * 2) = r;
        if (WRITE_B) {
            float2 s; s.x = di * r.x; s.y = di * r.y;
            __nv_bfloat162 b = __float22bfloat162_rn(s);
            *reinterpret_cast<__nv_bfloat162*>(outb + (size_t)warp * 32 + sub * 2) = b;
        }
    }
}

// ---------------------------------------------------------------------------
// C == 4 prop of zpack (dis-scaled [z1|z2]).
// ---------------------------------------------------------------------------
__global__ void prop_csr_c4(const float* __restrict__ zs, const float* __restrict__ dis,
                            const uint2* __restrict__ ed, const int* __restrict__ rs,
                            float* __restrict__ out, int N) {
    int warp = (blockIdx.x * blockDim.x + threadIdx.x) >> 5;
    int lane = threadIdx.x & 31;
    if (warp >= N) return;
    int k = lane >> 2;
    int c = lane & 3;
    int beg = rs[warp], end = rs[warp + 1];
    float acc = 0.f;
    for (int j = beg + k; j < end; j += 8) {
        uint2 e = ed[j];
        acc = fmaf(__uint_as_float(e.y), __ldg(zs + (size_t)e.x * 4 + c), acc);
    }
#pragma unroll
    for (int off = 16; off >= 4; off >>= 1)
        acc += __shfl_down_sync(0xffffffffu, acc, off);
    if (lane < 4) {
        float di = dis[warp];
        float r = -di * acc;
        out[(size_t)warp * 4 + c] = (c < 2) ? r : di * r;
    }
}

// ---------------------------------------------------------------------------
// Final tail: y = part + t4[:,0:2] + 2 * (-dis[d] * sum ea * t4[s, 2+c])
// ---------------------------------------------------------------------------
__global__ void prop2_final_k(const float* __restrict__ t4, const float* __restrict__ part,
                              const float* __restrict__ dis,
                              const uint2* __restrict__ ed, const int* __restrict__ rs,
                              float* __restrict__ y, int N) {
    int warp = (blockIdx.x * blockDim.x + threadIdx.x) >> 5;
    int lane = threadIdx.x & 31;
    if (warp >= N) return;
    int k = lane >> 1;
    int c = lane & 1;
    int beg = rs[warp], end = rs[warp + 1];
    float acc = 0.f;
    for (int j = beg + k; j < end; j += 16) {
        uint2 e = ed[j];
        acc = fmaf(__uint_as_float(e.y), __ldg(t4 + (size_t)e.x * 4 + 2 + c), acc);
    }
#pragma unroll
    for (int off = 16; off >= 2; off >>= 1)
        acc += __shfl_down_sync(0xffffffffu, acc, off);
    if (lane < 2) {
        float w = -dis[warp] * acc;
        y[(size_t)warp * 2 + c] = part[(size_t)warp * 2 + c]
                                + t4[(size_t)warp * 4 + c] + 2.f * w;
    }
}

// ---------------------------------------------------------------------------
// Layer-4 head GEMM: part = h@W0 - h@W2 ; zpack = dis[n]*[h@W1 | h@W2]
// ---------------------------------------------------------------------------
__global__ void gemm_head_64_2(const float* __restrict__ h, const float* __restrict__ dis,
                               const float* __restrict__ W,
                               float* __restrict__ part, float* __restrict__ zpack, int n) {
    __shared__ float sW[6 * 64];
    for (int i = threadIdx.x; i < 384; i += blockDim.x) {
        int k = i / 128, rem = i % 128, ci = rem / 2, co = rem % 2;
        sW[(k * 2 + co) * 64 + ci] = W[i];
    }
    __syncthreads();
    int warp = (blockIdx.x * blockDim.x + threadIdx.x) >> 5;
    int lane = threadIdx.x & 31;
    if (warp >= n) return;
    size_t base = (size_t)warp * 64;
    float a0 = h[base + lane];
    float a1 = h[base + lane + 32];
    float r[6];
#pragma unroll
    for (int m = 0; m < 6; m++) {
        const float* w = sW + m * 64;
        float acc = fmaf(a1, w[lane + 32], a0 * w[lane]);
#pragma unroll
        for (int off = 16; off > 0; off >>= 1)
            acc += __shfl_down_sync(0xffffffffu, acc, off);
        r[m] = acc;
    }
    if (lane == 0) {
        float di = dis[warp];
        part[(size_t)warp * 2 + 0] = r[0] - r[4];
        part[(size_t)warp * 2 + 1] = r[1] - r[5];
        float4 z; z.x = di * r[2]; z.y = di * r[3]; z.z = di * r[4]; z.w = di * r[5];
        *reinterpret_cast<float4*>(zpack + (size_t)warp * 4) = z;
    }
}

// ---------------------------------------------------------------------------
// Combine 1->16: emits fp32 out and dis-scaled bf16 shadow
// ---------------------------------------------------------------------------
__global__ void combine_1_16(const float* __restrict__ f0, const float* __restrict__ t1,
                             const float* __restrict__ t2, const float* __restrict__ dis,
                             const float* __restrict__ W,
                             float* __restrict__ out, __nv_bfloat16* __restrict__ outb,
                             int n) {
    __shared__ float sW[48];
    if (threadIdx.x < 48) sW[threadIdx.x] = W[threadIdx.x];
    __syncthreads();
    int tid = blockIdx.x * blockDim.x + threadIdx.x;
    int node = tid >> 4;
    int co = tid & 15;
    if (node >= n) return;
    float a = f0[node];
    float b = t1[node];
    float d = 2.f * t2[node] - a;
    float acc = a * sW[co] + b * sW[16 + co] + d * sW[32 + co];
    float r = fmaxf(acc, 0.f);
    out[(size_t)node * 16 + co] = r;
    outb[(size_t)node * 16 + co] = __float2bfloat16_rn(dis[node] * r);
}

// ---------------------------------------------------------------------------
// Combine 16->32: warp per node; emits dis-scaled bf16 shadow
// ---------------------------------------------------------------------------
__global__ void combine_16_32(const float* __restrict__ f0, const float* __restrict__ t1,
                              const float* __restrict__ t2, const float* __restrict__ dis,
                              const float* __restrict__ W,
                              float* __restrict__ out, __nv_bfloat16* __restrict__ outb,
                              int n) {
    __shared__ float sW[3 * 16 * 32];
    for (int i = threadIdx.x; i < 3 * 16 * 32; i += blockDim.x) sW[i] = W[i];
    __syncthreads();
    int warp = (blockIdx.x * blockDim.x + threadIdx.x) >> 5;
    int lane = threadIdx.x & 31;
    if (warp >= n) return;
    int c = lane & 15;
    float a = f0[(size_t)warp * 16 + c];
    float b = t1[(size_t)warp * 16 + c];
    float d = 2.f * t2[(size_t)warp * 16 + c] - a;
    float acc = 0.f;
#pragma unroll
    for (int cc = 0; cc < 16; cc++) {
        float av = __shfl_sync(0xffffffffu, a, cc);
        float bv = __shfl_sync(0xffffffffu, b, cc);
        float dv = __shfl_sync(0xffffffffu, d, cc);
        acc = fmaf(av, sW[cc * 32 + lane], acc);
        acc = fmaf(bv, sW[512 + cc * 32 + lane], acc);
        acc = fmaf(dv, sW[1024 + cc * 32 + lane], acc);
    }
    float r = fmaxf(acc, 0.f);
    out[(size_t)warp * 32 + lane] = r;
    outb[(size_t)warp * 32 + lane] = __float2bfloat16_rn(dis[warp] * r);
}

// ---------------------------------------------------------------------------
// Combine 32->64: warp per node; lane computes couts {2L, 2L+1} via LDS.64
// ---------------------------------------------------------------------------
__global__ void combine_32_64(const float* __restrict__ f0, const float* __restrict__ t1,
                              const float* __restrict__ t2, const float* __restrict__ W,
                              float* __restrict__ out, int n) {
    __shared__ float sW[3 * 32 * 64];
    for (int i = threadIdx.x; i < 3 * 32 * 64; i += blockDim.x) sW[i] = W[i];
    __syncthreads();
    int warp = (blockIdx.x * blockDim.x + threadIdx.x) >> 5;
    int lane = threadIdx.x & 31;
    if (warp >= n) return;
    float a = f0[(size_t)warp * 32 + lane];
    float b = t1[(size_t)warp * 32 + lane];
    float d = 2.f * t2[(size_t)warp * 32 + lane] - a;
    float acc0 = 0.f, acc1 = 0.f;
#pragma unroll
    for (int cc = 0; cc < 32; cc++) {
        float av = __shfl_sync(0xffffffffu, a, cc);
        float bv = __shfl_sync(0xffffffffu, b, cc);
        float dv = __shfl_sync(0xffffffffu, d, cc);
        float2 w0 = *reinterpret_cast<const float2*>(sW + cc * 64 + lane * 2);
        float2 w1 = *reinterpret_cast<const float2*>(sW + 2048 + cc * 64 + lane * 2);
        float2 w2 = *reinterpret_cast<const float2*>(sW + 4096 + cc * 64 + lane * 2);
        acc0 = fmaf(av, w0.x, acc0);
        acc1 = fmaf(av, w0.y, acc1);
        acc0 = fmaf(bv, w1.x, acc0);
        acc1 = fmaf(bv, w1.y, acc1);
        acc0 = fmaf(dv, w2.x, acc0);
        acc1 = fmaf(dv, w2.y, acc1);
    }
    float2 r; r.x = fmaxf(acc0, 0.f); r.y = fmaxf(acc1, 0.f);
    *reinterpret_cast<float2*>(out + (size_t)warp * 64 + lane * 2) = r;
}

extern "C" void kernel_launch(void* const* d_in, const int* in_sizes, int n_in,
                              void* d_out, int out_size) {
    const float* x = (const float*)d_in[0];
    const int* edge_index = (const int*)d_in[1];
    const float* ea = (const float*)d_in[2];
    const float* W1 = (const float*)d_in[3];
    const float* W2 = (const float*)d_in[4];
    const float* W3 = (const float*)d_in[5];
    const float* W4 = (const float*)d_in[6];

    const int N = in_sizes[0];
    const int E = in_sizes[2];
    const int* src = edge_index;
    const int* dst = edge_index + E;

    float *deg, *dis, *xs, *bufA, *bufB, *t1, *t1s, *t2;
    int *cnt, *rs, *cur;
    unsigned long long* sstate;
    uint2* edges;
    __nv_bfloat16 *xb, *tb;
    cudaGetSymbolAddress((void**)&deg, g_deg);
    cudaGetSymbolAddress((void**)&dis, g_dis);
    cudaGetSymbolAddress((void**)&xs, g_xs);
    cudaGetSymbolAddress((void**)&cnt, g_cnt);
    cudaGetSymbolAddress((void**)&rs, g_rs);
    cudaGetSymbolAddress((void**)&cur, g_cur);
    cudaGetSymbolAddress((void**)&sstate, g_sstate);
    cudaGetSymbolAddress((void**)&edges, g_edges);
    cudaGetSymbolAddress((void**)&bufA, g_bufA);
    cudaGetSymbolAddress((void**)&bufB, g_bufB);
    cudaGetSymbolAddress((void**)&t1, g_t1);
    cudaGetSymbolAddress((void**)&t1s, g_t1s);
    cudaGetSymbolAddress((void**)&t2, g_t2);
    cudaGetSymbolAddress((void**)&xb, g_xb);
    cudaGetSymbolAddress((void**)&tb, g_tb);

    // ---- build CSR + dis ----
    zero_build_k<<<cdiv(N, 256), 256>>>(deg, cnt, sstate, N);
    deg_hist_k<<<cdiv(cdiv(E, 4), 256), 256>>>(src, dst, ea, deg, cnt, E);
    int nb = cdiv(N, SCAN_ELEMS);
    scan_lookback_k<<<nb, SCAN_TPB>>>(cnt, sstate, rs, cur, N);
    scatter_k<<<cdiv(cdiv(E, 4), 256), 256>>>(src, dst, ea, cur, edges, E);
    dis_k<<<cdiv(N, 256), 256>>>(deg, x, dis, xs, N);

    const int WPB = 256;
    int grid_n = cdiv((long long)N * 32, WPB);

    // ---- layer 1: 1 -> 16, relu ----
    prop_c1<true><<<grid_n, WPB>>>(xs, dis, edges, rs, t1, t1s, N);
    prop_c1<false><<<grid_n, WPB>>>(t1s, dis, edges, rs, t2, nullptr, N);
    combine_1_16<<<cdiv((long long)N * 16, 256), 256>>>(x, t1, t2, dis, W1, bufA, xb, N);

    // ---- layer 2: 16 -> 32, relu (bf16 gathers) ----
    prop_c16_bf16<true><<<grid_n, WPB>>>(xb, dis, edges, rs, t1, tb, N);
    prop_c16_bf16<false><<<grid_n, WPB>>>(tb, dis, edges, rs, t2, nullptr, N);
    combine_16_32<<<grid_n, WPB>>>(bufA, t1, t2, dis, W2, bufB, xb, N);

    // ---- layer 3: 32 -> 64, relu (bf16 gathers) ----
    prop_c32_bf16<true><<<grid_n, WPB>>>(xb, dis, edges, rs, t1, tb, N);
    prop_c32_bf16<false><<<grid_n, WPB>>>(tb, dis, edges, rs, t2, nullptr, N);
    combine_32_64<<<grid_n, WPB>>>(bufB, t1, t2, W3, bufA, N);

    // ---- layer 4: 64 -> 2 via project-then-propagate ----
    gemm_head_64_2<<<grid_n, WPB>>>(bufA, dis, W4, bufB, t1, N);
    prop_csr_c4<<<grid_n, WPB>>>(t1, dis, edges, rs, t2, N);
    prop2_final_k<<<grid_n, WPB>>>(t2, bufB, dis, edges, rs, (float*)d_out, N);
}